// round 4
// baseline (speedup 1.0000x reference)
#include <cuda_runtime.h>
#include <cuda_fp16.h>
#include <cstdint>

#define VOCAB 32000
#define HID   128
#define BATCH 4
#define SEQT  2048
#define BT    (BATCH*SEQT)

// ---------------- scratch (static device globals; no runtime allocation) ----------------
__device__ __align__(16) float g_c0[BT*HID];
__device__ __align__(16) float g_c1[BT*HID];
__device__ __align__(16) float g_y0[BT*HID];
__device__ __align__(16) __half g_yhi[BT*HID];
__device__ __align__(16) __half g_ylo[BT*HID];
__device__ __align__(16) __half g_whi[VOCAB*HID];
__device__ __align__(16) __half g_wlo[VOCAB*HID];
__device__ int g_is64;

// ---------------- dtype probe ----------------
__global__ void detect_kernel(const int* x32) {
    if (threadIdx.x == 0) {
        int acc = 0;
        #pragma unroll
        for (int i = 0; i < 64; i++) acc |= x32[2*i + 1];
        g_is64 = (acc == 0) ? 1 : 0;
    }
}

// ---------------- fc_w -> fp16 split ----------------
__global__ void wsplit_kernel(const float* __restrict__ w) {
    int i = blockIdx.x * blockDim.x + threadIdx.x;
    if (i < VOCAB*HID) {
        float v = w[i];
        __half hi = __float2half_rn(v);
        g_whi[i] = hi;
        g_wlo[i] = __float2half_rn(v - __half2float(hi));
    }
}

// ---------------- input projection ----------------
__global__ __launch_bounds__(128) void proj_kernel(
    const void* __restrict__ xin, const float* __restrict__ emb,
    const float* __restrict__ W, const float* __restrict__ ba,
    const float* __restrict__ bb, int layer)
{
    __shared__ float sx[32][HID];
    const int j = threadIdx.x;
    const int chunk = blockIdx.x;

    float w[HID];
    #pragma unroll
    for (int k = 0; k < HID; k += 4) {
        float4 v = *(const float4*)(W + j*HID + k);
        w[k] = v.x; w[k+1] = v.y; w[k+2] = v.z; w[k+3] = v.w;
    }

    if (layer == 0) {
        const int is64 = g_is64;
        for (int r = 0; r < 32; r++) {
            int bt = chunk*32 + r;
            long long idx = is64 ? ((const long long*)xin)[bt]
                                 : (long long)((const int*)xin)[bt];
            sx[r][j] = emb[idx*HID + j];
        }
    } else {
        for (int r = 0; r < 32; r++) {
            int bt = chunk*32 + r;
            sx[r][j] = g_y0[bt*HID + j];
        }
    }
    __syncthreads();

    const float bias = ba[j] + bb[j];
    float* outc = (layer == 0) ? g_c0 : g_c1;
    for (int r = 0; r < 32; r++) {
        float acc = bias;
        #pragma unroll
        for (int k = 0; k < HID; k += 4) {
            float4 h4 = *(const float4*)&sx[r][k];
            acc += w[k]*h4.x + w[k+1]*h4.y + w[k+2]*h4.z + w[k+3]*h4.w;
        }
        outc[(chunk*32 + r)*HID + j] = acc;
    }
}

// ---------------- recurrent chain: one CTA per batch ----------------
typedef unsigned long long ull;

__device__ __forceinline__ float fast_tanh(float s) {
    float ax = fabsf(s);
    float e  = __expf(-2.0f * ax);                  // MUFU.EX2 path, branch-free
    float th = __fdividef(1.0f - e, 1.0f + e);      // MUFU.RCP path, branch-free
    return copysignf(th, s);
}

__global__ __launch_bounds__(128, 1) void chain_kernel(
    const float* __restrict__ Whh, const float* __restrict__ h0,
    float* __restrict__ hout, int layer)
{
    __shared__ __align__(16) float sh[2][HID];
    const int b = blockIdx.x;
    const int j = threadIdx.x;

    ull w2[HID/2];
    #pragma unroll
    for (int k = 0; k < HID/2; k++)
        w2[k] = ((const ull*)(Whh + j*HID))[k];

    sh[0][j] = h0[b*HID + j];
    __syncthreads();

    const float* cb = (layer == 0 ? g_c0 : g_c1) + (size_t)b*SEQT*HID;
    float c_pre0 = cb[j];
    float c_pre1 = cb[HID + j];

    for (int t = 0; t < SEQT; t++) {
        const float cc = c_pre0;
        c_pre0 = c_pre1;
        if (t + 2 < SEQT) c_pre1 = __ldg(&cb[(size_t)(t+2)*HID + j]);   // 2-step prefetch

        // 32 x LDS.128 broadcast; 4 independent packed accumulator chains
        const longlong2* hb = (const longlong2*)sh[t & 1];
        ull a0 = 0ull, a1 = 0ull, a2 = 0ull, a3 = 0ull;
        #pragma unroll
        for (int k = 0; k < 8; k++) {
            longlong2 h0v = hb[k];
            longlong2 h1v = hb[k + 8];
            longlong2 h2v = hb[k + 16];
            longlong2 h3v = hb[k + 24];
            asm("fma.rn.f32x2 %0, %1, %2, %0;" : "+l"(a0) : "l"(w2[2*k]),      "l"((ull)h0v.x));
            asm("fma.rn.f32x2 %0, %1, %2, %0;" : "+l"(a0) : "l"(w2[2*k+1]),    "l"((ull)h0v.y));
            asm("fma.rn.f32x2 %0, %1, %2, %0;" : "+l"(a1) : "l"(w2[2*k+16]),   "l"((ull)h1v.x));
            asm("fma.rn.f32x2 %0, %1, %2, %0;" : "+l"(a1) : "l"(w2[2*k+17]),   "l"((ull)h1v.y));
            asm("fma.rn.f32x2 %0, %1, %2, %0;" : "+l"(a2) : "l"(w2[2*k+32]),   "l"((ull)h2v.x));
            asm("fma.rn.f32x2 %0, %1, %2, %0;" : "+l"(a2) : "l"(w2[2*k+33]),   "l"((ull)h2v.y));
            asm("fma.rn.f32x2 %0, %1, %2, %0;" : "+l"(a3) : "l"(w2[2*k+48]),   "l"((ull)h3v.x));
            asm("fma.rn.f32x2 %0, %1, %2, %0;" : "+l"(a3) : "l"(w2[2*k+49]),   "l"((ull)h3v.y));
        }
        // packed reduction tree
        ull s01, s23, sall;
        asm("add.rn.f32x2 %0, %1, %2;" : "=l"(s01)  : "l"(a0),  "l"(a1));
        asm("add.rn.f32x2 %0, %1, %2;" : "=l"(s23)  : "l"(a2),  "l"(a3));
        asm("add.rn.f32x2 %0, %1, %2;" : "=l"(sall) : "l"(s01), "l"(s23));
        float s = cc + __uint_as_float((unsigned)sall)
                     + __uint_as_float((unsigned)(sall >> 32));
        float hn = fast_tanh(s);

        sh[(t + 1) & 1][j] = hn;
        const int bt = b*SEQT + t;
        if (layer == 0) {
            g_y0[bt*HID + j] = hn;
        } else {
            __half hi = __float2half_rn(hn);
            g_yhi[bt*HID + j] = hi;
            g_ylo[bt*HID + j] = __float2half_rn(hn - __half2float(hi));
        }
        __syncthreads();
    }
    hout[b*HID + j] = sh[SEQT & 1][j];
}

// ---------------- fc GEMM: split-fp16 mma.sync, tile 128x256, whole K resident ----------------
#define BM 128
#define BN 256
#define ROWB 272
#define A_TILE (128*ROWB)
#define B_TILE (256*ROWB)
#define OFF_A 1024
#define OFF_B (OFF_A + 2*A_TILE)
#define FC_SMEM (OFF_B + 2*B_TILE)

__device__ __forceinline__ void ldsm_x4(uint32_t addr, uint32_t& r0, uint32_t& r1,
                                        uint32_t& r2, uint32_t& r3) {
    asm volatile("ldmatrix.sync.aligned.m8n8.x4.shared.b16 {%0,%1,%2,%3}, [%4];"
                 : "=r"(r0), "=r"(r1), "=r"(r2), "=r"(r3) : "r"(addr));
}
__device__ __forceinline__ void mma16816(float* c, uint32_t a0, uint32_t a1,
                                         uint32_t a2, uint32_t a3,
                                         uint32_t b0, uint32_t b1) {
    asm volatile("mma.sync.aligned.m16n8k16.row.col.f32.f16.f16.f32 "
        "{%0,%1,%2,%3}, {%4,%5,%6,%7}, {%8,%9}, {%0,%1,%2,%3};"
        : "+f"(c[0]), "+f"(c[1]), "+f"(c[2]), "+f"(c[3])
        : "r"(a0), "r"(a1), "r"(a2), "r"(a3), "r"(b0), "r"(b1));
}

__global__ __launch_bounds__(512) void fc_kernel(const float* __restrict__ fc_b,
                                                 float* __restrict__ out) {
    extern __shared__ char sm[];
    const int tid = threadIdx.x;
    const int n0 = blockIdx.x * BN;
    const int m0 = blockIdx.y * BM;

    if (tid < 256) ((float*)sm)[tid] = fc_b[n0 + tid];

    for (int i = tid; i < 128*16; i += 512) {
        int r = i >> 4, c = i & 15;
        *(uint4*)(sm + OFF_A + r*ROWB + c*16) =
            ((const uint4*)(g_yhi + (size_t)(m0+r)*HID))[c];
        *(uint4*)(sm + OFF_A + A_TILE + r*ROWB + c*16) =
            ((const uint4*)(g_ylo + (size_t)(m0+r)*HID))[c];
    }
    for (int i = tid; i < 256*16; i += 512) {
        int r = i >> 4, c = i & 15;
        *(uint4*)(sm + OFF_B + r*ROWB + c*16) =
            ((const uint4*)(g_whi + (size_t)(n0+r)*HID))[c];
        *(uint4*)(sm + OFF_B + B_TILE + r*ROWB + c*16) =
            ((const uint4*)(g_wlo + (size_t)(n0+r)*HID))[c];
    }
    __syncthreads();

    const int lane = tid & 31, wid = tid >> 5;
    const int wm = wid >> 2, wn = wid & 3;
    const uint32_t smem_base = (uint32_t)__cvta_generic_to_shared(sm);

    const uint32_t a_base = smem_base + OFF_A + (wm*32 + (lane & 15))*ROWB + (lane >> 4)*16;
    const uint32_t b_base = smem_base + OFF_B + (wn*64 + (lane & 15))*ROWB + (lane >> 4)*16;

    float acc[2][8][4];
    #pragma unroll
    for (int mi = 0; mi < 2; mi++)
        #pragma unroll
        for (int ni = 0; ni < 8; ni++)
            #pragma unroll
            for (int q = 0; q < 4; q++) acc[mi][ni][q] = 0.f;

    const int apass[3] = {0, 1, 0};
    const int bpass[3] = {0, 0, 1};

    #pragma unroll
    for (int p = 0; p < 3; p++) {
        const uint32_t ao = a_base + apass[p]*A_TILE;
        const uint32_t bo = b_base + bpass[p]*B_TILE;
        #pragma unroll
        for (int k0 = 0; k0 < 8; k0++) {
            const uint32_t kb = k0*32;
            uint32_t a[2][4];
            ldsm_x4(ao + kb,            a[0][0], a[0][1], a[0][2], a[0][3]);
            ldsm_x4(ao + 16*ROWB + kb,  a[1][0], a[1][1], a[1][2], a[1][3]);
            uint32_t bfr[8][2];
            #pragma unroll
            for (int np = 0; np < 4; np++) {
                uint32_t r0, r1, r2, r3;
                ldsm_x4(bo + np*(16*ROWB) + kb, r0, r1, r2, r3);
                bfr[2*np][0]   = r0; bfr[2*np][1]   = r2;
                bfr[2*np+1][0] = r1; bfr[2*np+1][1] = r3;
            }
            #pragma unroll
            for (int mi = 0; mi < 2; mi++)
                #pragma unroll
                for (int ni = 0; ni < 8; ni++)
                    mma16816(acc[mi][ni], a[mi][0], a[mi][1], a[mi][2], a[mi][3],
                             bfr[ni][0], bfr[ni][1]);
        }
    }

    const float* bias = (const float*)sm;
    const int r_lo = m0 + wm*32 + (lane >> 2);
    #pragma unroll
    for (int mi = 0; mi < 2; mi++) {
        #pragma unroll
        for (int ni = 0; ni < 8; ni++) {
            const int col = wn*64 + ni*8 + (lane & 3)*2;
            const float b0 = bias[col], b1 = bias[col + 1];
            float2 v0 = make_float2(acc[mi][ni][0] + b0, acc[mi][ni][1] + b1);
            float2 v1 = make_float2(acc[mi][ni][2] + b0, acc[mi][ni][3] + b1);
            *(float2*)(out + (size_t)(r_lo + mi*16    )*VOCAB + n0 + col) = v0;
            *(float2*)(out + (size_t)(r_lo + mi*16 + 8)*VOCAB + n0 + col) = v1;
        }
    }
}

// ---------------- launch ----------------
extern "C" void kernel_launch(void* const* d_in, const int* in_sizes, int n_in,
                              void* d_out, int out_size) {
    const void*  x      = d_in[0];
    const float* hidden = (const float*)d_in[1];
    const float* emb    = (const float*)d_in[2];
    const float* W_ih0  = (const float*)d_in[3];
    const float* W_hh0  = (const float*)d_in[4];
    const float* b_ih0  = (const float*)d_in[5];
    const float* b_hh0  = (const float*)d_in[6];
    const float* W_ih1  = (const float*)d_in[7];
    const float* W_hh1  = (const float*)d_in[8];
    const float* b_ih1  = (const float*)d_in[9];
    const float* b_hh1  = (const float*)d_in[10];
    const float* fc_w   = (const float*)d_in[11];
    const float* fc_b   = (const float*)d_in[12];
    float* out = (float*)d_out;
    float* out_hidden = out + (size_t)BT * VOCAB;

    detect_kernel<<<1, 32>>>((const int*)x);
    wsplit_kernel<<<(VOCAB*HID + 255)/256, 256>>>(fc_w);
    proj_kernel<<<BT/32, 128>>>(x, emb, W_ih0, b_ih0, b_hh0, 0);
    chain_kernel<<<BATCH, 128>>>(W_hh0, hidden, out_hidden, 0);
    proj_kernel<<<BT/32, 128>>>(x, emb, W_ih1, b_ih1, b_hh1, 1);
    chain_kernel<<<BATCH, 128>>>(W_hh1, hidden + BATCH*HID, out_hidden + BATCH*HID, 1);

    cudaFuncSetAttribute(fc_kernel, cudaFuncAttributeMaxDynamicSharedMemorySize, FC_SMEM);
    fc_kernel<<<dim3(VOCAB/BN, BT/BM), 512, FC_SMEM>>>(fc_b, out);
}

// round 5
// speedup vs baseline: 1.1774x; 1.1774x over previous
#include <cuda_runtime.h>
#include <cuda_fp16.h>
#include <cstdint>

#define VOCAB 32000
#define HID   128
#define BATCH 4
#define SEQT  2048
#define BT    (BATCH*SEQT)

typedef unsigned long long ull;

// ---------------- scratch ----------------
__device__ __align__(16) float g_c0[BT*HID];        // layer0 input proj + biases
__device__ __align__(16) __half g_yhi[BT*HID];      // layer1 outputs split hi
__device__ __align__(16) __half g_ylo[BT*HID];      // layer1 outputs split lo
__device__ __align__(16) __half g_whi[VOCAB*HID];   // fc_w split hi
__device__ __align__(16) __half g_wlo[VOCAB*HID];   // fc_w split lo
__device__ int g_is64;

// ---------------- dtype probe ----------------
__global__ void detect_kernel(const int* x32) {
    if (threadIdx.x == 0) {
        int acc = 0;
        #pragma unroll
        for (int i = 0; i < 64; i++) acc |= x32[2*i + 1];
        g_is64 = (acc == 0) ? 1 : 0;
    }
}

// ---------------- fc_w -> fp16 split ----------------
__global__ void wsplit_kernel(const float* __restrict__ w) {
    int i = blockIdx.x * blockDim.x + threadIdx.x;
    if (i < VOCAB*HID) {
        float v = w[i];
        __half hi = __float2half_rn(v);
        g_whi[i] = hi;
        g_wlo[i] = __float2half_rn(v - __half2float(hi));
    }
}

// ---------------- layer0 input projection (embedding path only) ----------------
__global__ __launch_bounds__(128) void proj_kernel(
    const void* __restrict__ xin, const float* __restrict__ emb,
    const float* __restrict__ W, const float* __restrict__ ba,
    const float* __restrict__ bb)
{
    __shared__ float sx[32][HID];
    const int j = threadIdx.x;
    const int chunk = blockIdx.x;

    float w[HID];
    #pragma unroll
    for (int k = 0; k < HID; k += 4) {
        float4 v = *(const float4*)(W + j*HID + k);
        w[k] = v.x; w[k+1] = v.y; w[k+2] = v.z; w[k+3] = v.w;
    }

    const int is64 = g_is64;
    for (int r = 0; r < 32; r++) {
        int bt = chunk*32 + r;
        long long idx = is64 ? ((const long long*)xin)[bt]
                             : (long long)((const int*)xin)[bt];
        sx[r][j] = emb[idx*HID + j];
    }
    __syncthreads();

    const float bias = ba[j] + bb[j];
    for (int r = 0; r < 32; r++) {
        float acc = bias;
        #pragma unroll
        for (int k = 0; k < HID; k++) acc += w[k] * sx[r][k];
        g_c0[(chunk*32 + r)*HID + j] = acc;
    }
}

// ---------------- fused two-layer pipelined chain ----------------
__device__ __forceinline__ float fast_tanh(float s) {
    float ax = fabsf(s);
    float e  = __expf(-2.0f * ax);
    float th = __fdividef(1.0f - e, 1.0f + e);
    return copysignf(th, s);
}

__device__ __forceinline__ void lds_v2u64(uint32_t addr, ull& a, ull& b) {
    asm volatile("ld.shared.v2.u64 {%0,%1}, [%2];" : "=l"(a), "=l"(b) : "r"(addr));
}
__device__ __forceinline__ void fma2(ull& acc, ull w, ull h) {
    asm("fma.rn.f32x2 %0, %1, %2, %0;" : "+l"(acc) : "l"(w), "l"(h));
}

// dot of register row (64 ull) with 128-float smem vector at byte addr
__device__ __forceinline__ float dot128(const ull* w2, uint32_t hb) {
    ull a0 = 0ull, a1 = 0ull;
    #pragma unroll
    for (int k = 0; k < 16; k++) {
        ull p0, p1, q0, q1;
        lds_v2u64(hb + k*16,       p0, p1);
        lds_v2u64(hb + 256 + k*16, q0, q1);
        fma2(a0, w2[2*k],      p0);
        fma2(a0, w2[2*k + 1],  p1);
        fma2(a1, w2[2*k + 32], q0);
        fma2(a1, w2[2*k + 33], q1);
    }
    ull s;
    asm("add.rn.f32x2 %0, %1, %2;" : "=l"(s) : "l"(a0), "l"(a1));
    return __uint_as_float((unsigned)s) + __uint_as_float((unsigned)(s >> 32));
}

__global__ __launch_bounds__(384, 1) void fused_chain_kernel(
    const float* __restrict__ Whh0, const float* __restrict__ Wih1,
    const float* __restrict__ Whh1,
    const float* __restrict__ bih1, const float* __restrict__ bhh1,
    const float* __restrict__ hidden, float* __restrict__ hout)
{
    __shared__ __align__(16) float h0buf[2][HID];
    __shared__ __align__(16) float h1buf[2][HID];
    __shared__ __align__(16) float c1buf[2][HID];

    const int b   = blockIdx.x;
    const int tid = threadIdx.x;
    const int gid = tid >> 7;       // 0=A (layer0), 1=B1 (c1 proj), 2=B2 (layer1)
    const int j   = tid & 127;

    const uint32_t h0a = (uint32_t)__cvta_generic_to_shared(&h0buf[0][0]);
    const uint32_t h1a = (uint32_t)__cvta_generic_to_shared(&h1buf[0][0]);

    // per-group register weights
    ull w2[HID/2];
    {
        const float* wsrc = (gid == 0) ? Whh0 : (gid == 1) ? Wih1 : Whh1;
        #pragma unroll
        for (int k = 0; k < HID/2; k++)
            w2[k] = ((const ull*)(wsrc + j*HID))[k];
    }

    const float* cb = g_c0 + (size_t)b*SEQT*HID;
    float cpre0 = 0.f, cpre1 = 0.f, bias1 = 0.f;
    if (gid == 0) {
        h0buf[0][j] = hidden[b*HID + j];
        cpre0 = cb[j];
        cpre1 = cb[HID + j];
    } else if (gid == 1) {
        bias1 = bih1[j] + bhh1[j];
    } else {
        h1buf[0][j] = hidden[(BATCH + b)*HID + j];
    }
    __syncthreads();

    for (int i = 0; i < SEQT + 2; i++) {
        if (gid == 0) {
            if (i < SEQT) {
                const float cc = cpre0;
                cpre0 = cpre1;
                if (i + 2 < SEQT) cpre1 = __ldg(&cb[(size_t)(i+2)*HID + j]);
                float s  = cc + dot128(w2, h0a + (i & 1)*512);
                h0buf[(i + 1) & 1][j] = fast_tanh(s);
            }
        } else if (gid == 1) {
            if (i >= 1 && i <= SEQT) {
                // c1[s1] from h0[s1], s1 = i-1, stored by A in slot i&1
                c1buf[(i - 1) & 1][j] = bias1 + dot128(w2, h0a + (i & 1)*512);
            }
        } else {
            if (i >= 2) {
                const int s = i - 2;
                float sv = c1buf[s & 1][j] + dot128(w2, h1a + (s & 1)*512);
                float hn = fast_tanh(sv);
                h1buf[(s + 1) & 1][j] = hn;
                const size_t o = (size_t)(b*SEQT + s)*HID + j;
                __half hi = __float2half_rn(hn);
                g_yhi[o] = hi;
                g_ylo[o] = __float2half_rn(hn - __half2float(hi));
            }
        }
        __syncthreads();
    }

    if (gid == 0)      hout[b*HID + j]           = h0buf[SEQT & 1][j];
    else if (gid == 2) hout[(BATCH + b)*HID + j] = h1buf[SEQT & 1][j];
}

// ---------------- fc GEMM: split-fp16 mma.sync, tile 128x256, whole K resident ----------------
#define BM 128
#define BN 256
#define ROWB 272
#define A_TILE (128*ROWB)
#define B_TILE (256*ROWB)
#define OFF_A 1024
#define OFF_B (OFF_A + 2*A_TILE)
#define FC_SMEM (OFF_B + 2*B_TILE)

__device__ __forceinline__ void ldsm_x4(uint32_t addr, uint32_t& r0, uint32_t& r1,
                                        uint32_t& r2, uint32_t& r3) {
    asm volatile("ldmatrix.sync.aligned.m8n8.x4.shared.b16 {%0,%1,%2,%3}, [%4];"
                 : "=r"(r0), "=r"(r1), "=r"(r2), "=r"(r3) : "r"(addr));
}
__device__ __forceinline__ void mma16816(float* c, uint32_t a0, uint32_t a1,
                                         uint32_t a2, uint32_t a3,
                                         uint32_t b0, uint32_t b1) {
    asm volatile("mma.sync.aligned.m16n8k16.row.col.f32.f16.f16.f32 "
        "{%0,%1,%2,%3}, {%4,%5,%6,%7}, {%8,%9}, {%0,%1,%2,%3};"
        : "+f"(c[0]), "+f"(c[1]), "+f"(c[2]), "+f"(c[3])
        : "r"(a0), "r"(a1), "r"(a2), "r"(a3), "r"(b0), "r"(b1));
}

__global__ __launch_bounds__(512) void fc_kernel(const float* __restrict__ fc_b,
                                                 float* __restrict__ out) {
    extern __shared__ char sm[];
    const int tid = threadIdx.x;
    const int n0 = blockIdx.x * BN;
    const int m0 = blockIdx.y * BM;

    if (tid < 256) ((float*)sm)[tid] = fc_b[n0 + tid];

    for (int i = tid; i < 128*16; i += 512) {
        int r = i >> 4, c = i & 15;
        *(uint4*)(sm + OFF_A + r*ROWB + c*16) =
            ((const uint4*)(g_yhi + (size_t)(m0+r)*HID))[c];
        *(uint4*)(sm + OFF_A + A_TILE + r*ROWB + c*16) =
            ((const uint4*)(g_ylo + (size_t)(m0+r)*HID))[c];
    }
    for (int i = tid; i < 256*16; i += 512) {
        int r = i >> 4, c = i & 15;
        *(uint4*)(sm + OFF_B + r*ROWB + c*16) =
            ((const uint4*)(g_whi + (size_t)(n0+r)*HID))[c];
        *(uint4*)(sm + OFF_B + B_TILE + r*ROWB + c*16) =
            ((const uint4*)(g_wlo + (size_t)(n0+r)*HID))[c];
    }
    __syncthreads();

    const int lane = tid & 31, wid = tid >> 5;
    const int wm = wid >> 2, wn = wid & 3;
    const uint32_t smem_base = (uint32_t)__cvta_generic_to_shared(sm);

    const uint32_t a_base = smem_base + OFF_A + (wm*32 + (lane & 15))*ROWB + (lane >> 4)*16;
    const uint32_t b_base = smem_base + OFF_B + (wn*64 + (lane & 15))*ROWB + (lane >> 4)*16;

    float acc[2][8][4];
    #pragma unroll
    for (int mi = 0; mi < 2; mi++)
        #pragma unroll
        for (int ni = 0; ni < 8; ni++)
            #pragma unroll
            for (int q = 0; q < 4; q++) acc[mi][ni][q] = 0.f;

    const int apass[3] = {0, 1, 0};
    const int bpass[3] = {0, 0, 1};

    #pragma unroll
    for (int p = 0; p < 3; p++) {
        const uint32_t ao = a_base + apass[p]*A_TILE;
        const uint32_t bo = b_base + bpass[p]*B_TILE;
        #pragma unroll
        for (int k0 = 0; k0 < 8; k0++) {
            const uint32_t kb = k0*32;
            uint32_t a[2][4];
            ldsm_x4(ao + kb,            a[0][0], a[0][1], a[0][2], a[0][3]);
            ldsm_x4(ao + 16*ROWB + kb,  a[1][0], a[1][1], a[1][2], a[1][3]);
            uint32_t bfr[8][2];
            #pragma unroll
            for (int np = 0; np < 4; np++) {
                uint32_t r0, r1, r2, r3;
                ldsm_x4(bo + np*(16*ROWB) + kb, r0, r1, r2, r3);
                bfr[2*np][0]   = r0; bfr[2*np][1]   = r2;
                bfr[2*np+1][0] = r1; bfr[2*np+1][1] = r3;
            }
            #pragma unroll
            for (int mi = 0; mi < 2; mi++)
                #pragma unroll
                for (int ni = 0; ni < 8; ni++)
                    mma16816(acc[mi][ni], a[mi][0], a[mi][1], a[mi][2], a[mi][3],
                             bfr[ni][0], bfr[ni][1]);
        }
    }

    const float* bias = (const float*)sm;
    const int r_lo = m0 + wm*32 + (lane >> 2);
    #pragma unroll
    for (int mi = 0; mi < 2; mi++) {
        #pragma unroll
        for (int ni = 0; ni < 8; ni++) {
            const int col = wn*64 + ni*8 + (lane & 3)*2;
            const float b0 = bias[col], b1 = bias[col + 1];
            float2 v0 = make_float2(acc[mi][ni][0] + b0, acc[mi][ni][1] + b1);
            float2 v1 = make_float2(acc[mi][ni][2] + b0, acc[mi][ni][3] + b1);
            *(float2*)(out + (size_t)(r_lo + mi*16    )*VOCAB + n0 + col) = v0;
            *(float2*)(out + (size_t)(r_lo + mi*16 + 8)*VOCAB + n0 + col) = v1;
        }
    }
}

// ---------------- launch ----------------
extern "C" void kernel_launch(void* const* d_in, const int* in_sizes, int n_in,
                              void* d_out, int out_size) {
    const void*  x      = d_in[0];
    const float* hidden = (const float*)d_in[1];
    const float* emb    = (const float*)d_in[2];
    const float* W_ih0  = (const float*)d_in[3];
    const float* W_hh0  = (const float*)d_in[4];
    const float* b_ih0  = (const float*)d_in[5];
    const float* b_hh0  = (const float*)d_in[6];
    const float* W_ih1  = (const float*)d_in[7];
    const float* W_hh1  = (const float*)d_in[8];
    const float* b_ih1  = (const float*)d_in[9];
    const float* b_hh1  = (const float*)d_in[10];
    const float* fc_w   = (const float*)d_in[11];
    const float* fc_b   = (const float*)d_in[12];
    float* out = (float*)d_out;
    float* out_hidden = out + (size_t)BT * VOCAB;

    detect_kernel<<<1, 32>>>((const int*)x);
    wsplit_kernel<<<(VOCAB*HID + 255)/256, 256>>>(fc_w);
    proj_kernel<<<BT/32, 128>>>(x, emb, W_ih0, b_ih0, b_hh0);
    fused_chain_kernel<<<BATCH, 384>>>(W_hh0, W_ih1, W_hh1, b_ih1, b_hh1,
                                       hidden, out_hidden);

    cudaFuncSetAttribute(fc_kernel, cudaFuncAttributeMaxDynamicSharedMemorySize, FC_SMEM);
    fc_kernel<<<dim3(VOCAB/BN, BT/BM), 512, FC_SMEM>>>(fc_b, out);
}

// round 6
// speedup vs baseline: 1.4341x; 1.2180x over previous
#include <cuda_runtime.h>
#include <cuda_fp16.h>
#include <cstdint>

#define VOCAB 32000
#define HID   128
#define BATCH 4
#define SEQT  2048
#define BT    (BATCH*SEQT)
#define CH    32
#define NCH   (SEQT/CH)      // 64 chunks

// ---------------- scratch ----------------
__device__ __align__(16) float g_c0[BT*HID + 2*HID];   // layer0 input proj (+2-step pad)
__device__ __align__(16) float g_c1[BT*HID + 2*HID];   // layer1 input proj (+pad)
__device__ __align__(16) float g_h0[BT*HID];           // layer0 hidden outputs
__device__ __align__(16) __half g_yhi[BT*HID];
__device__ __align__(16) __half g_ylo[BT*HID];
__device__ __align__(16) __half g_whi[VOCAB*HID];
__device__ __align__(16) __half g_wlo[VOCAB*HID];
__device__ int g_is64;
__device__ int g_prog0[BATCH];          // layer0 progress (steps done)
__device__ int g_flag1[BATCH*NCH];      // c1 chunk-ready flags

// ---------------- sync helpers ----------------
__device__ __forceinline__ int ld_acq(const int* p) {
    int v;
    asm volatile("ld.acquire.gpu.global.s32 %0, [%1];" : "=r"(v) : "l"(p) : "memory");
    return v;
}
__device__ __forceinline__ void st_rel(int* p, int v) {
    asm volatile("st.release.gpu.global.s32 [%0], %1;" :: "l"(p), "r"(v) : "memory");
}

// ---------------- dtype probe + flag reset ----------------
__global__ void detect_kernel(const int* x32) {
    const int tid = threadIdx.x;
    if (tid == 0) {
        int acc = 0;
        #pragma unroll
        for (int i = 0; i < 64; i++) acc |= x32[2*i + 1];
        g_is64 = (acc == 0) ? 1 : 0;
    }
    if (tid < BATCH) g_prog0[tid] = 0;
    for (int i = tid; i < BATCH*NCH; i += 32) g_flag1[i] = 0;
}

// ---------------- fc_w -> fp16 split ----------------
__global__ void wsplit_kernel(const float* __restrict__ w) {
    int i = blockIdx.x * blockDim.x + threadIdx.x;
    if (i < VOCAB*HID) {
        float v = w[i];
        __half hi = __float2half_rn(v);
        g_whi[i] = hi;
        g_wlo[i] = __float2half_rn(v - __half2float(hi));
    }
}

// ---------------- layer0 input projection (embedding path) ----------------
__global__ __launch_bounds__(128) void proj_kernel(
    const void* __restrict__ xin, const float* __restrict__ emb,
    const float* __restrict__ W, const float* __restrict__ ba,
    const float* __restrict__ bb)
{
    __shared__ float sx[32][HID];
    const int j = threadIdx.x;
    const int chunk = blockIdx.x;

    float w[HID];
    #pragma unroll
    for (int k = 0; k < HID; k += 4) {
        float4 v = *(const float4*)(W + j*HID + k);
        w[k] = v.x; w[k+1] = v.y; w[k+2] = v.z; w[k+3] = v.w;
    }

    const int is64 = g_is64;
    for (int r = 0; r < 32; r++) {
        int bt = chunk*32 + r;
        long long idx = is64 ? ((const long long*)xin)[bt]
                             : (long long)((const int*)xin)[bt];
        sx[r][j] = emb[idx*HID + j];
    }
    __syncthreads();

    const float bias = ba[j] + bb[j];
    for (int r = 0; r < 32; r++) {
        float acc = bias;
        #pragma unroll
        for (int k = 0; k < HID; k++) acc += w[k] * sx[r][k];
        g_c0[(chunk*32 + r)*HID + j] = acc;
    }
}

// ---------------- math helpers ----------------
__device__ __forceinline__ float fast_tanh(float s) {
    float ax = fabsf(s);
    float e  = __expf(-2.0f * ax);
    float th = __fdividef(1.0f - e, 1.0f + e);
    return copysignf(th, s);
}

// scalar dot: 128-reg weights x smem vector (float4 loads, 8 acc chains)
__device__ __forceinline__ float dot128s(const float* w, const float* hs) {
    const float4* hb = (const float4*)hs;
    float a0=0,a1=0,a2=0,a3=0,a4=0,a5=0,a6=0,a7=0;
    #pragma unroll
    for (int k = 0; k < 8; k++) {
        float4 q0 = hb[k], q1 = hb[k+8], q2 = hb[k+16], q3 = hb[k+24];
        a0 += w[4*k+0]*q0.x;    a1 += w[4*k+1]*q0.y;
        a2 += w[4*k+2]*q0.z;    a3 += w[4*k+3]*q0.w;
        a4 += w[32+4*k+0]*q1.x; a5 += w[32+4*k+1]*q1.y;
        a6 += w[32+4*k+2]*q1.z; a7 += w[32+4*k+3]*q1.w;
        a0 += w[64+4*k+0]*q2.x; a1 += w[64+4*k+1]*q2.y;
        a2 += w[64+4*k+2]*q2.z; a3 += w[64+4*k+3]*q2.w;
        a4 += w[96+4*k+0]*q3.x; a5 += w[96+4*k+1]*q3.y;
        a6 += w[96+4*k+2]*q3.z; a7 += w[96+4*k+3]*q3.w;
    }
    return ((a0+a1)+(a2+a3)) + ((a4+a5)+(a6+a7));
}

// scalar dot: 128-reg weights x gmem vector (__ldg float4)
__device__ __forceinline__ float dot128g(const float* w, const float4* hr) {
    float a0=0,a1=0,a2=0,a3=0,a4=0,a5=0,a6=0,a7=0;
    #pragma unroll
    for (int k = 0; k < 8; k++) {
        float4 q0 = __ldg(hr+k), q1 = __ldg(hr+k+8),
               q2 = __ldg(hr+k+16), q3 = __ldg(hr+k+24);
        a0 += w[4*k+0]*q0.x;    a1 += w[4*k+1]*q0.y;
        a2 += w[4*k+2]*q0.z;    a3 += w[4*k+3]*q0.w;
        a4 += w[32+4*k+0]*q1.x; a5 += w[32+4*k+1]*q1.y;
        a6 += w[32+4*k+2]*q1.z; a7 += w[32+4*k+3]*q1.w;
        a0 += w[64+4*k+0]*q2.x; a1 += w[64+4*k+1]*q2.y;
        a2 += w[64+4*k+2]*q2.z; a3 += w[64+4*k+3]*q2.w;
        a4 += w[96+4*k+0]*q3.x; a5 += w[96+4*k+1]*q3.y;
        a6 += w[96+4*k+2]*q3.z; a7 += w[96+4*k+3]*q3.w;
    }
    return ((a0+a1)+(a2+a3)) + ((a4+a5)+(a6+a7));
}

// ---------------- pipelined multi-role kernel: 40 CTAs ----------------
// CTA 0..3   : layer0 recurrence, batch b = bid        (produces g_h0, g_prog0)
// CTA 4..35  : proj1 workers, 8 per batch, chunked     (produce g_c1, g_flag1)
// CTA 36..39 : layer1 recurrence, batch b = bid-36     (produce g_yhi/g_ylo, h1)
__global__ __launch_bounds__(128, 1) void pipe_kernel(
    const float* __restrict__ Whh0, const float* __restrict__ Wih1,
    const float* __restrict__ Whh1,
    const float* __restrict__ bih1, const float* __restrict__ bhh1,
    const float* __restrict__ hidden, float* __restrict__ hout)
{
    const int bid = blockIdx.x;
    const int j   = threadIdx.x;
    __shared__ __align__(16) float sh[2][HID];

    if (bid < 4) {
        // ---- layer0 chain ----
        const int b = bid;
        float w[HID];
        #pragma unroll
        for (int k = 0; k < HID; k += 4) {
            float4 v = *(const float4*)(Whh0 + j*HID + k);
            w[k] = v.x; w[k+1] = v.y; w[k+2] = v.z; w[k+3] = v.w;
        }
        sh[0][j] = hidden[b*HID + j];
        __syncthreads();

        const float* cb = g_c0 + (size_t)b*SEQT*HID;
        float cp0 = cb[j], cp1 = cb[HID + j];

        for (int t = 0; t < SEQT; t++) {
            const float cc = cp0;
            cp0 = cp1;
            cp1 = __ldg(&cb[(size_t)(t+2)*HID + j]);   // padded, unconditional

            float s  = cc + dot128s(w, sh[t & 1]);
            float hn = fast_tanh(s);
            sh[(t+1) & 1][j] = hn;
            g_h0[(size_t)(b*SEQT + t)*HID + j] = hn;
            __syncthreads();
            if (((t+1) & (CH-1)) == 0 && j == 0) {
                __threadfence();
                st_rel(&g_prog0[b], t + 1);
            }
        }
        hout[b*HID + j] = sh[SEQT & 1][j];

    } else if (bid < 36) {
        // ---- proj1 workers: c1 = W_ih1 . h0 + biases ----
        const int wi = bid - 4;
        const int b  = wi >> 3;
        float w[HID];
        #pragma unroll
        for (int k = 0; k < HID; k += 4) {
            float4 v = *(const float4*)(Wih1 + j*HID + k);
            w[k] = v.x; w[k+1] = v.y; w[k+2] = v.z; w[k+3] = v.w;
        }
        const float bias = bih1[j] + bhh1[j];

        for (int k = (wi & 7); k < NCH; k += 8) {
            const int target = (k + 1) * CH;
            if (j == 0) {
                while (ld_acq(&g_prog0[b]) < target) __nanosleep(128);
            }
            __syncthreads();
            for (int t = k*CH; t < (k+1)*CH; t++) {
                const size_t bt = (size_t)(b*SEQT + t);
                const float4* hr = (const float4*)(g_h0 + bt*HID);
                g_c1[bt*HID + j] = bias + dot128g(w, hr);
            }
            __syncthreads();
            if (j == 0) {
                __threadfence();
                st_rel(&g_flag1[b*NCH + k], 1);
            }
        }

    } else {
        // ---- layer1 chain ----
        const int b = bid - 36;
        float w[HID];
        #pragma unroll
        for (int k = 0; k < HID; k += 4) {
            float4 v = *(const float4*)(Whh1 + j*HID + k);
            w[k] = v.x; w[k+1] = v.y; w[k+2] = v.z; w[k+3] = v.w;
        }
        sh[0][j] = hidden[(BATCH + b)*HID + j];

        // wait for chunks 0 and 1 before first loads
        if (j == 0) {
            while (ld_acq(&g_flag1[b*NCH + 0]) == 0) __nanosleep(128);
            while (ld_acq(&g_flag1[b*NCH + 1]) == 0) __nanosleep(128);
        }
        __syncthreads();

        const float* cb = g_c1 + (size_t)b*SEQT*HID;
        float cp0 = cb[j], cp1 = cb[HID + j];

        for (int t = 0; t < SEQT; t++) {
            if ((t & (CH-1)) == 0 && t > 0) {
                const int kn = min((t >> 5) + 1, NCH - 1);
                if (j == 0) {
                    while (ld_acq(&g_flag1[b*NCH + kn]) == 0) __nanosleep(128);
                }
                __syncthreads();
            }
            const float cc = cp0;
            cp0 = cp1;
            cp1 = __ldg(&cb[(size_t)(t+2)*HID + j]);   // safe: chunk kn flagged

            float s  = cc + dot128s(w, sh[t & 1]);
            float hn = fast_tanh(s);
            sh[(t+1) & 1][j] = hn;
            const size_t o = (size_t)(b*SEQT + t)*HID + j;
            __half hi = __float2half_rn(hn);
            g_yhi[o] = hi;
            g_ylo[o] = __float2half_rn(hn - __half2float(hi));
            __syncthreads();
        }
        hout[(BATCH + b)*HID + j] = sh[SEQT & 1][j];
    }
}

// ---------------- fc GEMM: split-fp16 mma.sync, tile 128x256, whole K resident ----------------
#define BM 128
#define BN 256
#define ROWB 272
#define A_TILE (128*ROWB)
#define B_TILE (256*ROWB)
#define OFF_A 1024
#define OFF_B (OFF_A + 2*A_TILE)
#define FC_SMEM (OFF_B + 2*B_TILE)

__device__ __forceinline__ void ldsm_x4(uint32_t addr, uint32_t& r0, uint32_t& r1,
                                        uint32_t& r2, uint32_t& r3) {
    asm volatile("ldmatrix.sync.aligned.m8n8.x4.shared.b16 {%0,%1,%2,%3}, [%4];"
                 : "=r"(r0), "=r"(r1), "=r"(r2), "=r"(r3) : "r"(addr));
}
__device__ __forceinline__ void mma16816(float* c, uint32_t a0, uint32_t a1,
                                         uint32_t a2, uint32_t a3,
                                         uint32_t b0, uint32_t b1) {
    asm volatile("mma.sync.aligned.m16n8k16.row.col.f32.f16.f16.f32 "
        "{%0,%1,%2,%3}, {%4,%5,%6,%7}, {%8,%9}, {%0,%1,%2,%3};"
        : "+f"(c[0]), "+f"(c[1]), "+f"(c[2]), "+f"(c[3])
        : "r"(a0), "r"(a1), "r"(a2), "r"(a3), "r"(b0), "r"(b1));
}

__global__ __launch_bounds__(512) void fc_kernel(const float* __restrict__ fc_b,
                                                 float* __restrict__ out) {
    extern __shared__ char sm[];
    const int tid = threadIdx.x;
    const int n0 = blockIdx.x * BN;
    const int m0 = blockIdx.y * BM;

    if (tid < 256) ((float*)sm)[tid] = fc_b[n0 + tid];

    for (int i = tid; i < 128*16; i += 512) {
        int r = i >> 4, c = i & 15;
        *(uint4*)(sm + OFF_A + r*ROWB + c*16) =
            ((const uint4*)(g_yhi + (size_t)(m0+r)*HID))[c];
        *(uint4*)(sm + OFF_A + A_TILE + r*ROWB + c*16) =
            ((const uint4*)(g_ylo + (size_t)(m0+r)*HID))[c];
    }
    for (int i = tid; i < 256*16; i += 512) {
        int r = i >> 4, c = i & 15;
        *(uint4*)(sm + OFF_B + r*ROWB + c*16) =
            ((const uint4*)(g_whi + (size_t)(n0+r)*HID))[c];
        *(uint4*)(sm + OFF_B + B_TILE + r*ROWB + c*16) =
            ((const uint4*)(g_wlo + (size_t)(n0+r)*HID))[c];
    }
    __syncthreads();

    const int lane = tid & 31, wid = tid >> 5;
    const int wm = wid >> 2, wn = wid & 3;
    const uint32_t smem_base = (uint32_t)__cvta_generic_to_shared(sm);

    const uint32_t a_base = smem_base + OFF_A + (wm*32 + (lane & 15))*ROWB + (lane >> 4)*16;
    const uint32_t b_base = smem_base + OFF_B + (wn*64 + (lane & 15))*ROWB + (lane >> 4)*16;

    float acc[2][8][4];
    #pragma unroll
    for (int mi = 0; mi < 2; mi++)
        #pragma unroll
        for (int ni = 0; ni < 8; ni++)
            #pragma unroll
            for (int q = 0; q < 4; q++) acc[mi][ni][q] = 0.f;

    const int apass[3] = {0, 1, 0};
    const int bpass[3] = {0, 0, 1};

    #pragma unroll
    for (int p = 0; p < 3; p++) {
        const uint32_t ao = a_base + apass[p]*A_TILE;
        const uint32_t bo = b_base + bpass[p]*B_TILE;
        #pragma unroll
        for (int k0 = 0; k0 < 8; k0++) {
            const uint32_t kb = k0*32;
            uint32_t a[2][4];
            ldsm_x4(ao + kb,            a[0][0], a[0][1], a[0][2], a[0][3]);
            ldsm_x4(ao + 16*ROWB + kb,  a[1][0], a[1][1], a[1][2], a[1][3]);
            uint32_t bfr[8][2];
            #pragma unroll
            for (int np = 0; np < 4; np++) {
                uint32_t r0, r1, r2, r3;
                ldsm_x4(bo + np*(16*ROWB) + kb, r0, r1, r2, r3);
                bfr[2*np][0]   = r0; bfr[2*np][1]   = r2;
                bfr[2*np+1][0] = r1; bfr[2*np+1][1] = r3;
            }
            #pragma unroll
            for (int mi = 0; mi < 2; mi++)
                #pragma unroll
                for (int ni = 0; ni < 8; ni++)
                    mma16816(acc[mi][ni], a[mi][0], a[mi][1], a[mi][2], a[mi][3],
                             bfr[ni][0], bfr[ni][1]);
        }
    }

    const float* bias = (const float*)sm;
    const int r_lo = m0 + wm*32 + (lane >> 2);
    #pragma unroll
    for (int mi = 0; mi < 2; mi++) {
        #pragma unroll
        for (int ni = 0; ni < 8; ni++) {
            const int col = wn*64 + ni*8 + (lane & 3)*2;
            const float b0 = bias[col], b1 = bias[col + 1];
            float2 v0 = make_float2(acc[mi][ni][0] + b0, acc[mi][ni][1] + b1);
            float2 v1 = make_float2(acc[mi][ni][2] + b0, acc[mi][ni][3] + b1);
            *(float2*)(out + (size_t)(r_lo + mi*16    )*VOCAB + n0 + col) = v0;
            *(float2*)(out + (size_t)(r_lo + mi*16 + 8)*VOCAB + n0 + col) = v1;
        }
    }
}

// ---------------- launch ----------------
extern "C" void kernel_launch(void* const* d_in, const int* in_sizes, int n_in,
                              void* d_out, int out_size) {
    const void*  x      = d_in[0];
    const float* hidden = (const float*)d_in[1];
    const float* emb    = (const float*)d_in[2];
    const float* W_ih0  = (const float*)d_in[3];
    const float* W_hh0  = (const float*)d_in[4];
    const float* b_ih0  = (const float*)d_in[5];
    const float* b_hh0  = (const float*)d_in[6];
    const float* W_ih1  = (const float*)d_in[7];
    const float* W_hh1  = (const float*)d_in[8];
    const float* b_ih1  = (const float*)d_in[9];
    const float* b_hh1  = (const float*)d_in[10];
    const float* fc_w   = (const float*)d_in[11];
    const float* fc_b   = (const float*)d_in[12];
    float* out = (float*)d_out;
    float* out_hidden = out + (size_t)BT * VOCAB;

    detect_kernel<<<1, 32>>>((const int*)x);
    wsplit_kernel<<<(VOCAB*HID + 255)/256, 256>>>(fc_w);
    proj_kernel<<<BT/32, 128>>>(x, emb, W_ih0, b_ih0, b_hh0);
    pipe_kernel<<<40, 128>>>(W_hh0, W_ih1, W_hh1, b_ih1, b_hh1,
                             hidden, out_hidden);

    cudaFuncSetAttribute(fc_kernel, cudaFuncAttributeMaxDynamicSharedMemorySize, FC_SMEM);
    fc_kernel<<<dim3(VOCAB/BN, BT/BM), 512, FC_SMEM>>>(fc_b, out);
}